// round 11
// baseline (speedup 1.0000x reference)
#include <cuda_runtime.h>
#include <cuda_bf16.h>
#include <math.h>
#include <stdint.h>

#define NB 8192
#define ND 256
#define BM 128
#define BN 128
#define BK 64
#define NTILE 64            // NB/BM
#define NBLK 2080           // NTILE*(NTILE+1)/2
#define RSB 1024            // row_stats blocks

// exp(sim/T) = exp2(sim * (log2e / T))
#define CEXP 20.6099291551f

// ---------------- scratch (no allocations allowed) ----------------
__device__ __nv_bfloat16 g_fbf[NB * ND];
__device__ float  g_dsq[NB];
__device__ float  g_accL0[NB];
__device__ float  g_accT[NB];
__device__ double p_sum[RSB], p_ssq[RSB], p_ctr[RSB];
__device__ int    p_cnt[RSB];
__device__ double g_center_d;
__device__ float  g_m;
__device__ int    g_cnt;
__device__ unsigned g_tick_rs, g_tick_cm;

// ---------------- helpers ----------------
__device__ __forceinline__ uint32_t smem_u32(const void* p) {
    uint32_t a;
    asm("{ .reg .u64 t; cvta.to.shared.u64 t, %1; cvt.u32.u64 %0, t; }" : "=r"(a) : "l"(p));
    return a;
}
__device__ __forceinline__ float ex2f(float x) {
    float y; asm("ex2.approx.ftz.f32 %0, %1;" : "=f"(y) : "f"(x)); return y;
}
__device__ __forceinline__ void cp_async16(uint32_t s, const void* g) {
    asm volatile("cp.async.cg.shared.global [%0], [%1], 16;" :: "r"(s), "l"(g));
}
__device__ __forceinline__ void ldsm_x4(uint32_t* r, uint32_t addr) {
    asm volatile("ldmatrix.sync.aligned.m8n8.x4.shared.b16 {%0,%1,%2,%3}, [%4];"
                 : "=r"(r[0]), "=r"(r[1]), "=r"(r[2]), "=r"(r[3]) : "r"(addr));
}
__device__ __forceinline__ void mma16816(float* c, const uint32_t* a,
                                         uint32_t b0, uint32_t b1) {
    asm volatile("mma.sync.aligned.m16n8k16.row.col.f32.bf16.bf16.f32 "
                 "{%0,%1,%2,%3}, {%4,%5,%6,%7}, {%8,%9}, {%0,%1,%2,%3};"
                 : "+f"(c[0]), "+f"(c[1]), "+f"(c[2]), "+f"(c[3])
                 : "r"(a[0]), "r"(a[1]), "r"(a[2]), "r"(a[3]), "r"(b0), "r"(b1));
}

// ---------------- pass 1: stats + bf16 normalize; last block does sigma ----
__global__ void row_stats(const float* __restrict__ feat,
                          const int*   __restrict__ lab,
                          const float* __restrict__ cen,
                          const float* __restrict__ rsig) {
    __shared__ double sh_sm[8], sh_ssq[8], sh_ctr[8];
    __shared__ int    sh_cnt[8];
    __shared__ int    s_last;
    int wrp  = threadIdx.x >> 5;
    int row  = blockIdx.x * 8 + wrp;
    int lane = threadIdx.x & 31;
    const float4* fr = (const float4*)(feat + (size_t)row * ND);
    const float4* cr = (const float4*)cen;

    float dsq = 0.f, ssq = 0.f, sm = 0.f;
    float v[8];
#pragma unroll
    for (int c = 0; c < 2; c++) {
        int d4 = c * 32 + lane;
        float4 x = fr[d4], cv = cr[d4];
        v[c*4+0] = x.x; v[c*4+1] = x.y; v[c*4+2] = x.z; v[c*4+3] = x.w;
        float dx = x.x - cv.x, dy = x.y - cv.y, dz = x.z - cv.z, dw = x.w - cv.w;
        dsq += dx*dx + dy*dy + dz*dz + dw*dw;
        ssq += x.x*x.x + x.y*x.y + x.z*x.z + x.w*x.w;
        sm  += x.x + x.y + x.z + x.w;
    }
#pragma unroll
    for (int o = 16; o > 0; o >>= 1) {
        dsq += __shfl_xor_sync(0xffffffffu, dsq, o);
        ssq += __shfl_xor_sync(0xffffffffu, ssq, o);
        sm  += __shfl_xor_sync(0xffffffffu, sm , o);
    }
    float inv_norm = 1.f / fmaxf(sqrtf(ssq), 1e-12f);
#pragma unroll
    for (int c = 0; c < 2; c++) {
        int d0 = (c * 32 + lane) * 4;
        __nv_bfloat162 p0 = __floats2bfloat162_rn(v[c*4+0]*inv_norm, v[c*4+1]*inv_norm);
        __nv_bfloat162 p1 = __floats2bfloat162_rn(v[c*4+2]*inv_norm, v[c*4+3]*inv_norm);
        uint2 pk; pk.x = *(uint32_t*)&p0; pk.y = *(uint32_t*)&p1;
        *(uint2*)&g_fbf[(size_t)row * ND + d0] = pk;
    }
    if (lane == 0) {
        g_dsq[row] = dsq;
        g_accL0[row] = 0.f;
        g_accT[row]  = 0.f;
        int isn = (lab[row] == 0);
        sh_sm[wrp]  = isn ? (double)sm  : 0.0;
        sh_ssq[wrp] = isn ? (double)ssq : 0.0;
        sh_ctr[wrp] = isn ? (double)dsq : 0.0;
        sh_cnt[wrp] = isn;
    }
    __syncthreads();
    if (threadIdx.x == 0) {
        double a = 0, b2 = 0, c2 = 0; int n = 0;
#pragma unroll
        for (int w = 0; w < 8; w++) { a += sh_sm[w]; b2 += sh_ssq[w]; c2 += sh_ctr[w]; n += sh_cnt[w]; }
        p_sum[blockIdx.x] = a; p_ssq[blockIdx.x] = b2;
        p_ctr[blockIdx.x] = c2; p_cnt[blockIdx.x] = n;
        __threadfence();
        unsigned t = atomicAdd(&g_tick_rs, 1u);
        s_last = (t == RSB - 1);
    }
    __syncthreads();

    if (s_last) {     // last block: reduce partials, compute sigma/margin
        __shared__ double r0[256], r1[256], r2[256];
        __shared__ int    r3[256];
        int t = threadIdx.x;
        double a = 0, b = 0, c = 0; int n = 0;
#pragma unroll
        for (int q = 0; q < RSB / 256; q++) {
            int idx = t + q * 256;
            a += p_sum[idx]; b += p_ssq[idx]; c += p_ctr[idx]; n += p_cnt[idx];
        }
        r0[t] = a; r1[t] = b; r2[t] = c; r3[t] = n;
        __syncthreads();
        for (int o = 128; o > 0; o >>= 1) {
            if (t < o) { r0[t] += r0[t+o]; r1[t] += r1[t+o]; r2[t] += r2[t+o]; r3[t] += r3[t+o]; }
            __syncthreads();
        }
        if (t == 0) {
            int cnt = r3[0];
            double n_el  = (double)cnt * (double)ND;
            double var   = (r1[0] - r0[0] * r0[0] / n_el) / (n_el - 1.0);
            double sigma = 0.9 * (double)rsig[0] + 0.1 * sqrt(var);
            g_m = (float)(0.5 + 0.3 * sigma + 0.3 * (1.0 - 224.0 / 900.0));
            g_center_d = r2[0];
            g_cnt = cnt;
            g_tick_rs = 0u;
        }
    }
}

// ---------------- pass 2: triangle-tiled bf16 mma contrastive ----------------
// 128x128 CTA tile, 4 warps (2x2), warp tile 64x64, BK=64, 3-stage cp.async.
// Last CTA (ticket) computes the final per-row log pass and writes out[0].
__global__ void __launch_bounds__(128, 2) contrast_mma(const int* __restrict__ lab,
                                                       float* __restrict__ out) {
    extern __shared__ __align__(16) char dsm[];
    __shared__ float s_w0c[BN];
    __shared__ float s_w0r[BM];
    __shared__ int s_last;

    // invert linear triangle index -> (ti, tj), tj >= ti
    int b = blockIdx.x;
    int ti = (int)((129.0 - sqrt(129.0 * 129.0 - 8.0 * (double)b)) * 0.5);
    int base = ti * NTILE - (ti * (ti - 1)) / 2;
    if (b < base) { ti--; base = ti * NTILE - (ti * (ti - 1)) / 2; }
    else if (b >= base + (NTILE - ti)) { ti++; base = ti * NTILE - (ti * (ti - 1)) / 2; }
    const int tj = ti + (b - base);

    const uint32_t sbase = smem_u32(dsm);
    const int tid = threadIdx.x, lane = tid & 31, wid = tid >> 5;
    const int wm = wid & 1, wn = wid >> 1;
    const int i0 = ti * BM, j0 = tj * BN;
    const bool diag = (ti == tj);

    for (int j = tid; j < BN; j += 128)
        s_w0c[j] = (lab[j0 + j] == 0) ? 1.f : 0.f;
    for (int i = tid; i < BM; i += 128)
        s_w0r[i] = (lab[i0 + i] == 0) ? 1.f : 0.f;

    float c[4][8][4];
#pragma unroll
    for (int fm = 0; fm < 4; fm++)
#pragma unroll
        for (int fn = 0; fn < 8; fn++)
#pragma unroll
            for (int e = 0; e < 4; e++) c[fm][fn][e] = 0.f;

    auto prefetch = [&](int kb) {
        uint32_t a_s = sbase + (uint32_t)(kb % 3) * 32768u;
        uint32_t b_s = a_s + 16384u;
        const __nv_bfloat16* gA = g_fbf + (size_t)i0 * ND + kb * BK;
        const __nv_bfloat16* gB = g_fbf + (size_t)j0 * ND + kb * BK;
#pragma unroll
        for (int it = 0; it < 8; it++) {
            int ch = tid + it * 128;             // 1024 chunks per tile
            int row = ch >> 3, c16 = ch & 7;
            uint32_t sw = (uint32_t)(row * 128 + ((c16 ^ (row & 7)) << 4));
            cp_async16(a_s + sw, gA + (size_t)row * ND + c16 * 8);
            cp_async16(b_s + sw, gB + (size_t)row * ND + c16 * 8);
        }
        asm volatile("cp.async.commit_group;" ::: "memory");
    };

    prefetch(0);
    prefetch(1);

#pragma unroll 1
    for (int kb = 0; kb < ND / BK; kb++) {
        if (kb < ND / BK - 1)
            asm volatile("cp.async.wait_group 1;" ::: "memory");
        else
            asm volatile("cp.async.wait_group 0;" ::: "memory");
        __syncthreads();
        if (kb + 2 < ND / BK) prefetch(kb + 2);

        uint32_t a_s = sbase + (uint32_t)(kb % 3) * 32768u;
        uint32_t b_s = a_s + 16384u;

#pragma unroll
        for (int ks = 0; ks < 4; ks++) {
            uint32_t a_frag[4][4], b_frag[4][4];
            int c16 = ks * 2 + (lane >> 4);
#pragma unroll
            for (int fm = 0; fm < 4; fm++) {
                int row = wm * 64 + fm * 16 + (lane & 15);
                ldsm_x4(a_frag[fm], a_s + row * 128 + ((c16 ^ (row & 7)) << 4));
            }
#pragma unroll
            for (int g = 0; g < 4; g++) {
                int row = wn * 64 + g * 16 + (lane & 15);
                ldsm_x4(b_frag[g], b_s + row * 128 + ((c16 ^ (row & 7)) << 4));
            }
#pragma unroll
            for (int fm = 0; fm < 4; fm++)
#pragma unroll
                for (int fn = 0; fn < 8; fn++) {
                    int g = fn >> 1;
                    uint32_t b0 = (fn & 1) ? b_frag[g][1] : b_frag[g][0];
                    uint32_t b1 = (fn & 1) ? b_frag[g][3] : b_frag[g][2];
                    mma16816(c[fm][fn], a_frag[fm], b0, b1);
                }
        }
    }

    // ---- epilogue ----
    const int rl = wm * 64 + (lane >> 2);
    const int r_base = i0 + rl;
    float racc[16];
#pragma unroll
    for (int q = 0; q < 16; q++) racc[q] = 0.f;

    if (!diag) {
#pragma unroll
        for (int fn = 0; fn < 8; fn++) {
            int jl = wn * 64 + fn * 8 + (lane & 3) * 2;
            float w0a = s_w0c[jl], w0b = s_w0c[jl + 1];
            float cTa = 0.f, cTb = 0.f, c0a = 0.f, c0b = 0.f;
#pragma unroll
            for (int fm = 0; fm < 4; fm++) {
                float e00 = ex2f(c[fm][fn][0] * CEXP);
                float e01 = ex2f(c[fm][fn][1] * CEXP);
                float e10 = ex2f(c[fm][fn][2] * CEXP);
                float e11 = ex2f(c[fm][fn][3] * CEXP);
                racc[fm*4+0] = fmaf(e00, w0a, fmaf(e01, w0b, racc[fm*4+0]));
                racc[fm*4+1] += e00 + e01;
                racc[fm*4+2] = fmaf(e10, w0a, fmaf(e11, w0b, racc[fm*4+2]));
                racc[fm*4+3] += e10 + e11;
                float wrA = s_w0r[rl + fm * 16], wrB = s_w0r[rl + fm * 16 + 8];
                cTa += e00 + e10; cTb += e01 + e11;
                c0a = fmaf(e00, wrA, fmaf(e10, wrB, c0a));
                c0b = fmaf(e01, wrA, fmaf(e11, wrB, c0b));
            }
#pragma unroll
            for (int o = 4; o <= 16; o <<= 1) {
                cTa += __shfl_xor_sync(0xffffffffu, cTa, o);
                cTb += __shfl_xor_sync(0xffffffffu, cTb, o);
                c0a += __shfl_xor_sync(0xffffffffu, c0a, o);
                c0b += __shfl_xor_sync(0xffffffffu, c0b, o);
            }
            if ((lane >> 2) == 0) {
                int jc = j0 + wn * 64 + fn * 8 + lane * 2;
                atomicAdd(&g_accT[jc],      cTa);
                atomicAdd(&g_accT[jc + 1],  cTb);
                atomicAdd(&g_accL0[jc],     c0a);
                atomicAdd(&g_accL0[jc + 1], c0b);
            }
        }
    } else {
#pragma unroll
        for (int fn = 0; fn < 8; fn++) {
            int jl = wn * 64 + fn * 8 + (lane & 3) * 2;
            int jg = j0 + jl;
            float w0a = s_w0c[jl], w0b = s_w0c[jl + 1];
#pragma unroll
            for (int fm = 0; fm < 4; fm++) {
                int r0 = r_base + fm * 16, r1 = r0 + 8;
                float e00 = ex2f(c[fm][fn][0] * CEXP);
                float e01 = ex2f(c[fm][fn][1] * CEXP);
                float e10 = ex2f(c[fm][fn][2] * CEXP);
                float e11 = ex2f(c[fm][fn][3] * CEXP);
                if (r0 == jg)     e00 = 0.f;
                if (r0 == jg + 1) e01 = 0.f;
                if (r1 == jg)     e10 = 0.f;
                if (r1 == jg + 1) e11 = 0.f;
                racc[fm*4+0] = fmaf(e00, w0a, fmaf(e01, w0b, racc[fm*4+0]));
                racc[fm*4+1] += e00 + e01;
                racc[fm*4+2] = fmaf(e10, w0a, fmaf(e11, w0b, racc[fm*4+2]));
                racc[fm*4+3] += e10 + e11;
            }
        }
    }

#pragma unroll
    for (int o = 1; o < 4; o <<= 1)
#pragma unroll
        for (int q = 0; q < 16; q++)
            racc[q] += __shfl_xor_sync(0xffffffffu, racc[q], o);

    if ((lane & 3) == 0) {
#pragma unroll
        for (int fm = 0; fm < 4; fm++) {
            int r0 = r_base + fm * 16, r1 = r0 + 8;
            atomicAdd(&g_accL0[r0], racc[fm*4+0]);
            atomicAdd(&g_accT[r0],  racc[fm*4+1]);
            atomicAdd(&g_accL0[r1], racc[fm*4+2]);
            atomicAdd(&g_accT[r1],  racc[fm*4+3]);
        }
    }

    // ---- ticket tail: last CTA computes final loss ----
    __syncthreads();                     // all epilogue atomics of this CTA issued
    if (tid == 0) {
        __threadfence();
        unsigned t = atomicAdd(&g_tick_cm, 1u);
        s_last = (t == NBLK - 1);
    }
    __syncthreads();
    if (s_last) {
        __shared__ double red[128];
        int n0 = g_cnt, n1 = NB - n0;
        float m = g_m;
        double acc = 0.0;
#pragma unroll 1
        for (int i = tid; i < NB; i += 128) {
            int li = lab[i];
            float aT = g_accT[i], a0 = g_accL0[i];
            float pos = (li == 0) ? a0 : (aT - a0);
            int npos = ((li == 0) ? n0 : n1) - 1;
            int nneg = (li == 0) ? n1 : n0;
            float loc = 0.f;
            if (npos > 0 && nneg > 0)
                loc = 0.5f * (logf(aT + 1e-8f) - logf(pos));   // GAMMA*r_con
            if (li == 1)
                loc += fmaxf(m - sqrtf(g_dsq[i]), 0.f);        // BETA*r_margin
            acc += (double)loc;
        }
        red[tid] = acc;
        __syncthreads();
        for (int o = 64; o > 0; o >>= 1) {
            if (tid < o) red[tid] += red[tid + o];
            __syncthreads();
        }
        if (tid == 0) {
            g_tick_cm = 0u;
            out[0] = (float)((g_center_d + red[0]) / (double)NB);
        }
    }
}

// ---------------- launch ----------------
extern "C" void kernel_launch(void* const* d_in, const int* in_sizes, int n_in,
                              void* d_out, int out_size) {
    const float* feat = (const float*)d_in[0];
    const int*   lab  = (const int*)d_in[1];
    const float* cen  = (const float*)d_in[2];
    const float* rsig = (const float*)d_in[3];
    float* out = (float*)d_out;

    cudaFuncSetAttribute(contrast_mma,
                         cudaFuncAttributeMaxDynamicSharedMemorySize, 98304);

    row_stats<<<RSB, 256>>>(feat, lab, cen, rsig);
    contrast_mma<<<NBLK, 128, 98304>>>(lab, out);
}

// round 12
// speedup vs baseline: 1.1899x; 1.1899x over previous
#include <cuda_runtime.h>
#include <cuda_bf16.h>
#include <math.h>
#include <stdint.h>

#define NB 8192
#define ND 256
#define BM 128
#define BN 128
#define BK 64
#define NTILE 64            // NB/BM
#define NBLK 2080           // NTILE*(NTILE+1)/2
#define RSB 256             // row_stats blocks (32 rows each)

// exp(sim/T) = exp2(sim * (log2e / T))
#define CEXP 20.6099291551f

// ---------------- scratch (no allocations allowed) ----------------
__device__ __nv_bfloat16 g_fbf[NB * ND];
__device__ float  g_dsq[NB];
__device__ float  g_accL0[NB];
__device__ float  g_accT[NB];
__device__ double p_sum[RSB], p_ssq[RSB], p_ctr[RSB];
__device__ int    p_cnt[RSB];
__device__ double g_center_d;
__device__ float  g_m;
__device__ int    g_cnt;
__device__ unsigned g_tick_rs, g_tick_cm;

// ---------------- helpers ----------------
__device__ __forceinline__ uint32_t smem_u32(const void* p) {
    uint32_t a;
    asm("{ .reg .u64 t; cvta.to.shared.u64 t, %1; cvt.u32.u64 %0, t; }" : "=r"(a) : "l"(p));
    return a;
}
__device__ __forceinline__ float ex2f(float x) {
    float y; asm("ex2.approx.ftz.f32 %0, %1;" : "=f"(y) : "f"(x)); return y;
}
__device__ __forceinline__ void cp_async16(uint32_t s, const void* g) {
    asm volatile("cp.async.cg.shared.global [%0], [%1], 16;" :: "r"(s), "l"(g));
}
__device__ __forceinline__ void ldsm_x4(uint32_t* r, uint32_t addr) {
    asm volatile("ldmatrix.sync.aligned.m8n8.x4.shared.b16 {%0,%1,%2,%3}, [%4];"
                 : "=r"(r[0]), "=r"(r[1]), "=r"(r[2]), "=r"(r[3]) : "r"(addr));
}
__device__ __forceinline__ void mma16816(float* c, const uint32_t* a,
                                         uint32_t b0, uint32_t b1) {
    asm volatile("mma.sync.aligned.m16n8k16.row.col.f32.bf16.bf16.f32 "
                 "{%0,%1,%2,%3}, {%4,%5,%6,%7}, {%8,%9}, {%0,%1,%2,%3};"
                 : "+f"(c[0]), "+f"(c[1]), "+f"(c[2]), "+f"(c[3])
                 : "r"(a[0]), "r"(a[1]), "r"(a[2]), "r"(a[3]), "r"(b0), "r"(b1));
}

// ---------------- pass 1: stats + bf16 normalize (4 rows/warp, MLP=8) ------
__global__ void row_stats(const float* __restrict__ feat,
                          const int*   __restrict__ lab,
                          const float* __restrict__ cen,
                          const float* __restrict__ rsig) {
    __shared__ double sh_sm[8], sh_ssq[8], sh_ctr[8];
    __shared__ int    sh_cnt[8];
    __shared__ int    s_last;
    const int wrp  = threadIdx.x >> 5;
    const int lane = threadIdx.x & 31;
    const int row0 = blockIdx.x * 32 + wrp * 4;

    const float4* cr = (const float4*)cen;
    float4 cv0 = cr[lane], cv1 = cr[32 + lane];

    // issue all 8 row-chunk loads up front (independent -> MLP 8)
    float4 x[4][2];
#pragma unroll
    for (int r = 0; r < 4; r++) {
        const float4* fr = (const float4*)(feat + (size_t)(row0 + r) * ND);
        x[r][0] = fr[lane];
        x[r][1] = fr[32 + lane];
    }

    double wsum = 0.0, wssq = 0.0, wctr = 0.0;
    int    wcnt = 0;
#pragma unroll
    for (int r = 0; r < 4; r++) {
        int row = row0 + r;
        float dsq = 0.f, ssq = 0.f, sm = 0.f;
#pragma unroll
        for (int c = 0; c < 2; c++) {
            float4 v = x[r][c], cv = c ? cv1 : cv0;
            float dx = v.x - cv.x, dy = v.y - cv.y, dz = v.z - cv.z, dw = v.w - cv.w;
            dsq += dx*dx + dy*dy + dz*dz + dw*dw;
            ssq += v.x*v.x + v.y*v.y + v.z*v.z + v.w*v.w;
            sm  += v.x + v.y + v.z + v.w;
        }
#pragma unroll
        for (int o = 16; o > 0; o >>= 1) {
            dsq += __shfl_xor_sync(0xffffffffu, dsq, o);
            ssq += __shfl_xor_sync(0xffffffffu, ssq, o);
            sm  += __shfl_xor_sync(0xffffffffu, sm , o);
        }
        float inv_norm = 1.f / fmaxf(sqrtf(ssq), 1e-12f);
#pragma unroll
        for (int c = 0; c < 2; c++) {
            float4 v = x[r][c];
            int d0 = (c * 32 + lane) * 4;
            __nv_bfloat162 p0 = __floats2bfloat162_rn(v.x*inv_norm, v.y*inv_norm);
            __nv_bfloat162 p1 = __floats2bfloat162_rn(v.z*inv_norm, v.w*inv_norm);
            uint2 pk; pk.x = *(uint32_t*)&p0; pk.y = *(uint32_t*)&p1;
            *(uint2*)&g_fbf[(size_t)row * ND + d0] = pk;
        }
        if (lane == 0) {
            g_dsq[row] = dsq;
            g_accL0[row] = 0.f;
            g_accT[row]  = 0.f;
            if (lab[row] == 0) {
                wsum += (double)sm; wssq += (double)ssq;
                wctr += (double)dsq; wcnt++;
            }
        }
    }
    if (lane == 0) {
        sh_sm[wrp] = wsum; sh_ssq[wrp] = wssq; sh_ctr[wrp] = wctr; sh_cnt[wrp] = wcnt;
    }
    __syncthreads();
    if (threadIdx.x == 0) {
        double a = 0, b2 = 0, c2 = 0; int n = 0;
#pragma unroll
        for (int w = 0; w < 8; w++) { a += sh_sm[w]; b2 += sh_ssq[w]; c2 += sh_ctr[w]; n += sh_cnt[w]; }
        p_sum[blockIdx.x] = a; p_ssq[blockIdx.x] = b2;
        p_ctr[blockIdx.x] = c2; p_cnt[blockIdx.x] = n;
        __threadfence();
        unsigned t = atomicAdd(&g_tick_rs, 1u);
        s_last = (t == RSB - 1);
    }
    __syncthreads();

    if (s_last) {     // last block: reduce partials, compute sigma/margin
        __shared__ double r0[256], r1[256], r2[256];
        __shared__ int    r3[256];
        int t = threadIdx.x;
        r0[t] = p_sum[t]; r1[t] = p_ssq[t]; r2[t] = p_ctr[t]; r3[t] = p_cnt[t];
        __syncthreads();
        for (int o = 128; o > 0; o >>= 1) {
            if (t < o) { r0[t] += r0[t+o]; r1[t] += r1[t+o]; r2[t] += r2[t+o]; r3[t] += r3[t+o]; }
            __syncthreads();
        }
        if (t == 0) {
            int cnt = r3[0];
            double n_el  = (double)cnt * (double)ND;
            double var   = (r1[0] - r0[0] * r0[0] / n_el) / (n_el - 1.0);
            double sigma = 0.9 * (double)rsig[0] + 0.1 * sqrt(var);
            g_m = (float)(0.5 + 0.3 * sigma + 0.3 * (1.0 - 224.0 / 900.0));
            g_center_d = r2[0];
            g_cnt = cnt;
            g_tick_rs = 0u;
        }
    }
}

// ---------------- pass 2: triangle-tiled bf16 mma contrastive ----------------
// 128x128 CTA tile, 8 warps (4x2), warp tile 32x64, BK=64, 3-stage cp.async.
// Last CTA (ticket) computes the final per-row log pass and writes out[0].
__global__ void __launch_bounds__(256, 2) contrast_mma(const int* __restrict__ lab,
                                                       float* __restrict__ out) {
    extern __shared__ __align__(16) char dsm[];
    __shared__ float s_w0c[BN];
    __shared__ float s_w0r[BM];
    __shared__ int s_last;

    // invert linear triangle index -> (ti, tj), tj >= ti
    int b = blockIdx.x;
    int ti = (int)((129.0 - sqrt(129.0 * 129.0 - 8.0 * (double)b)) * 0.5);
    int base = ti * NTILE - (ti * (ti - 1)) / 2;
    if (b < base) { ti--; base = ti * NTILE - (ti * (ti - 1)) / 2; }
    else if (b >= base + (NTILE - ti)) { ti++; base = ti * NTILE - (ti * (ti - 1)) / 2; }
    const int tj = ti + (b - base);

    const uint32_t sbase = smem_u32(dsm);
    const int tid = threadIdx.x, lane = tid & 31, wid = tid >> 5;
    const int wm = wid & 3, wn = wid >> 2;
    const int i0 = ti * BM, j0 = tj * BN;
    const bool diag = (ti == tj);

    for (int j = tid; j < BN; j += 256)
        s_w0c[j] = (lab[j0 + j] == 0) ? 1.f : 0.f;
    for (int i = tid; i < BM; i += 256)
        s_w0r[i] = (lab[i0 + i] == 0) ? 1.f : 0.f;

    float c[2][8][4];
#pragma unroll
    for (int fm = 0; fm < 2; fm++)
#pragma unroll
        for (int fn = 0; fn < 8; fn++)
#pragma unroll
            for (int e = 0; e < 4; e++) c[fm][fn][e] = 0.f;

    auto prefetch = [&](int kb) {
        uint32_t a_s = sbase + (uint32_t)(kb % 3) * 32768u;
        uint32_t b_s = a_s + 16384u;
        const __nv_bfloat16* gA = g_fbf + (size_t)i0 * ND + kb * BK;
        const __nv_bfloat16* gB = g_fbf + (size_t)j0 * ND + kb * BK;
#pragma unroll
        for (int it = 0; it < 4; it++) {
            int ch = tid + it * 256;
            int row = ch >> 3, c16 = ch & 7;
            uint32_t sw = (uint32_t)(row * 128 + ((c16 ^ (row & 7)) << 4));
            cp_async16(a_s + sw, gA + (size_t)row * ND + c16 * 8);
            cp_async16(b_s + sw, gB + (size_t)row * ND + c16 * 8);
        }
        asm volatile("cp.async.commit_group;" ::: "memory");
    };

    prefetch(0);
    prefetch(1);

#pragma unroll 1
    for (int kb = 0; kb < ND / BK; kb++) {
        if (kb < ND / BK - 1)
            asm volatile("cp.async.wait_group 1;" ::: "memory");
        else
            asm volatile("cp.async.wait_group 0;" ::: "memory");
        __syncthreads();
        if (kb + 2 < ND / BK) prefetch(kb + 2);

        uint32_t a_s = sbase + (uint32_t)(kb % 3) * 32768u;
        uint32_t b_s = a_s + 16384u;

#pragma unroll
        for (int ks = 0; ks < 4; ks++) {
            uint32_t a_frag[2][4], b_frag[4][4];
            int c16 = ks * 2 + (lane >> 4);
#pragma unroll
            for (int fm = 0; fm < 2; fm++) {
                int row = wm * 32 + fm * 16 + (lane & 15);
                ldsm_x4(a_frag[fm], a_s + row * 128 + ((c16 ^ (row & 7)) << 4));
            }
#pragma unroll
            for (int g = 0; g < 4; g++) {
                int row = wn * 64 + g * 16 + (lane & 15);
                ldsm_x4(b_frag[g], b_s + row * 128 + ((c16 ^ (row & 7)) << 4));
            }
#pragma unroll
            for (int fm = 0; fm < 2; fm++)
#pragma unroll
                for (int fn = 0; fn < 8; fn++) {
                    int g = fn >> 1;
                    uint32_t b0 = (fn & 1) ? b_frag[g][1] : b_frag[g][0];
                    uint32_t b1 = (fn & 1) ? b_frag[g][3] : b_frag[g][2];
                    mma16816(c[fm][fn], a_frag[fm], b0, b1);
                }
        }
    }

    // ---- epilogue (register-lean; fn outer, col partials short-lived) ----
    const int rl = wm * 32 + (lane >> 2);
    const int r_base = i0 + rl;
    float racc[8];
#pragma unroll
    for (int q = 0; q < 8; q++) racc[q] = 0.f;

    if (!diag) {
        float wr0 = s_w0r[rl], wr1 = s_w0r[rl + 8];
        float wr2 = s_w0r[rl + 16], wr3 = s_w0r[rl + 24];
#pragma unroll
        for (int fn = 0; fn < 8; fn++) {
            int jl = wn * 64 + fn * 8 + (lane & 3) * 2;
            float w0a = s_w0c[jl], w0b = s_w0c[jl + 1];
            float cTa = 0.f, cTb = 0.f, c0a = 0.f, c0b = 0.f;
#pragma unroll
            for (int fm = 0; fm < 2; fm++) {
                float e00 = ex2f(c[fm][fn][0] * CEXP);
                float e01 = ex2f(c[fm][fn][1] * CEXP);
                float e10 = ex2f(c[fm][fn][2] * CEXP);
                float e11 = ex2f(c[fm][fn][3] * CEXP);
                racc[fm*4+0] = fmaf(e00, w0a, fmaf(e01, w0b, racc[fm*4+0]));
                racc[fm*4+1] += e00 + e01;
                racc[fm*4+2] = fmaf(e10, w0a, fmaf(e11, w0b, racc[fm*4+2]));
                racc[fm*4+3] += e10 + e11;
                float wrA = fm ? wr2 : wr0, wrB = fm ? wr3 : wr1;
                cTa += e00 + e10; cTb += e01 + e11;
                c0a = fmaf(e00, wrA, fmaf(e10, wrB, c0a));
                c0b = fmaf(e01, wrA, fmaf(e11, wrB, c0b));
            }
#pragma unroll
            for (int o = 4; o <= 16; o <<= 1) {
                cTa += __shfl_xor_sync(0xffffffffu, cTa, o);
                cTb += __shfl_xor_sync(0xffffffffu, cTb, o);
                c0a += __shfl_xor_sync(0xffffffffu, c0a, o);
                c0b += __shfl_xor_sync(0xffffffffu, c0b, o);
            }
            if ((lane >> 2) == 0) {
                int jc = j0 + wn * 64 + fn * 8 + lane * 2;
                atomicAdd(&g_accT[jc],      cTa);
                atomicAdd(&g_accT[jc + 1],  cTb);
                atomicAdd(&g_accL0[jc],     c0a);
                atomicAdd(&g_accL0[jc + 1], c0b);
            }
        }
    } else {
#pragma unroll
        for (int fn = 0; fn < 8; fn++) {
            int jl = wn * 64 + fn * 8 + (lane & 3) * 2;
            int jg = j0 + jl;
            float w0a = s_w0c[jl], w0b = s_w0c[jl + 1];
#pragma unroll
            for (int fm = 0; fm < 2; fm++) {
                int r0 = r_base + fm * 16, r1 = r0 + 8;
                float e00 = ex2f(c[fm][fn][0] * CEXP);
                float e01 = ex2f(c[fm][fn][1] * CEXP);
                float e10 = ex2f(c[fm][fn][2] * CEXP);
                float e11 = ex2f(c[fm][fn][3] * CEXP);
                if (r0 == jg)     e00 = 0.f;
                if (r0 == jg + 1) e01 = 0.f;
                if (r1 == jg)     e10 = 0.f;
                if (r1 == jg + 1) e11 = 0.f;
                racc[fm*4+0] = fmaf(e00, w0a, fmaf(e01, w0b, racc[fm*4+0]));
                racc[fm*4+1] += e00 + e01;
                racc[fm*4+2] = fmaf(e10, w0a, fmaf(e11, w0b, racc[fm*4+2]));
                racc[fm*4+3] += e10 + e11;
            }
        }
    }

#pragma unroll
    for (int o = 1; o < 4; o <<= 1)
#pragma unroll
        for (int q = 0; q < 8; q++)
            racc[q] += __shfl_xor_sync(0xffffffffu, racc[q], o);

    if ((lane & 3) == 0) {
#pragma unroll
        for (int fm = 0; fm < 2; fm++) {
            int r0 = r_base + fm * 16, r1 = r0 + 8;
            atomicAdd(&g_accL0[r0], racc[fm*4+0]);
            atomicAdd(&g_accT[r0],  racc[fm*4+1]);
            atomicAdd(&g_accL0[r1], racc[fm*4+2]);
            atomicAdd(&g_accT[r1],  racc[fm*4+3]);
        }
    }

    // ---- ticket tail: last CTA computes final loss ----
    __syncthreads();
    if (tid == 0) {
        __threadfence();
        unsigned t = atomicAdd(&g_tick_cm, 1u);
        s_last = (t == NBLK - 1);
    }
    __syncthreads();
    if (s_last) {
        __shared__ double red[256];
        int n0 = g_cnt, n1 = NB - n0;
        float m = g_m;
        double acc = 0.0;
#pragma unroll 1
        for (int i = tid; i < NB; i += 256) {
            int li = lab[i];
            float aT = g_accT[i], a0 = g_accL0[i];
            float pos = (li == 0) ? a0 : (aT - a0);
            int npos = ((li == 0) ? n0 : n1) - 1;
            int nneg = (li == 0) ? n1 : n0;
            float loc = 0.f;
            if (npos > 0 && nneg > 0)
                loc = 0.5f * (logf(aT + 1e-8f) - logf(pos));   // GAMMA*r_con
            if (li == 1)
                loc += fmaxf(m - sqrtf(g_dsq[i]), 0.f);        // BETA*r_margin
            acc += (double)loc;
        }
        red[tid] = acc;
        __syncthreads();
        for (int o = 128; o > 0; o >>= 1) {
            if (tid < o) red[tid] += red[tid + o];
            __syncthreads();
        }
        if (tid == 0) {
            g_tick_cm = 0u;
            out[0] = (float)((g_center_d + red[0]) / (double)NB);
        }
    }
}

// ---------------- launch ----------------
extern "C" void kernel_launch(void* const* d_in, const int* in_sizes, int n_in,
                              void* d_out, int out_size) {
    const float* feat = (const float*)d_in[0];
    const int*   lab  = (const int*)d_in[1];
    const float* cen  = (const float*)d_in[2];
    const float* rsig = (const float*)d_in[3];
    float* out = (float*)d_out;

    cudaFuncSetAttribute(contrast_mma,
                         cudaFuncAttributeMaxDynamicSharedMemorySize, 98304);

    row_stats<<<RSB, 256>>>(feat, lab, cen, rsig);
    contrast_mma<<<NBLK, 256, 98304>>>(lab, out);
}

// round 13
// speedup vs baseline: 1.7720x; 1.4892x over previous
#include <cuda_runtime.h>
#include <cuda_bf16.h>
#include <math.h>
#include <stdint.h>

#define NB 8192
#define ND 256
#define BM 128
#define BN 128
#define BK 64
#define NTILE 64            // NB/BM
#define NBLK 2080           // NTILE*(NTILE+1)/2
#define RSB 256             // row_stats blocks (32 rows each)

// exp(sim/T) = exp2(sim * (log2e / T))
#define CEXP 20.6099291551f

// ---------------- scratch (no allocations allowed) ----------------
__device__ __nv_bfloat16 g_fbf[NB * ND];
__device__ float  g_dsq[NB];
__device__ float  g_accL0[NB];
__device__ float  g_accT[NB];
__device__ double p_sum[RSB], p_ssq[RSB], p_ctr[RSB];
__device__ int    p_cnt[RSB];
__device__ double g_center_d, g_mc_d;
__device__ float  g_m;
__device__ int    g_cnt;
__device__ unsigned g_tick_rs, g_tick_cf;

// ---------------- helpers ----------------
__device__ __forceinline__ uint32_t smem_u32(const void* p) {
    uint32_t a;
    asm("{ .reg .u64 t; cvta.to.shared.u64 t, %1; cvt.u32.u64 %0, t; }" : "=r"(a) : "l"(p));
    return a;
}
__device__ __forceinline__ float ex2f(float x) {
    float y; asm("ex2.approx.ftz.f32 %0, %1;" : "=f"(y) : "f"(x)); return y;
}
__device__ __forceinline__ void cp_async16(uint32_t s, const void* g) {
    asm volatile("cp.async.cg.shared.global [%0], [%1], 16;" :: "r"(s), "l"(g));
}
__device__ __forceinline__ void ldsm_x4(uint32_t* r, uint32_t addr) {
    asm volatile("ldmatrix.sync.aligned.m8n8.x4.shared.b16 {%0,%1,%2,%3}, [%4];"
                 : "=r"(r[0]), "=r"(r[1]), "=r"(r[2]), "=r"(r[3]) : "r"(addr));
}
__device__ __forceinline__ void mma16816(float* c, const uint32_t* a,
                                         uint32_t b0, uint32_t b1) {
    asm volatile("mma.sync.aligned.m16n8k16.row.col.f32.bf16.bf16.f32 "
                 "{%0,%1,%2,%3}, {%4,%5,%6,%7}, {%8,%9}, {%0,%1,%2,%3};"
                 : "+f"(c[0]), "+f"(c[1]), "+f"(c[2]), "+f"(c[3])
                 : "r"(a[0]), "r"(a[1]), "r"(a[2]), "r"(a[3]), "r"(b0), "r"(b1));
}

// ---------------- pass 1: stats + bf16 normalize (4 rows/warp, MLP=8) ------
__global__ void row_stats(const float* __restrict__ feat,
                          const int*   __restrict__ lab,
                          const float* __restrict__ cen,
                          const float* __restrict__ rsig) {
    __shared__ double sh_sm[8], sh_ssq[8], sh_ctr[8];
    __shared__ int    sh_cnt[8];
    __shared__ int    s_last;
    const int wrp  = threadIdx.x >> 5;
    const int lane = threadIdx.x & 31;
    const int row0 = blockIdx.x * 32 + wrp * 4;

    const float4* cr = (const float4*)cen;
    float4 cv0 = cr[lane], cv1 = cr[32 + lane];

    float4 x[4][2];
#pragma unroll
    for (int r = 0; r < 4; r++) {
        const float4* fr = (const float4*)(feat + (size_t)(row0 + r) * ND);
        x[r][0] = fr[lane];
        x[r][1] = fr[32 + lane];
    }

    double wsum = 0.0, wssq = 0.0, wctr = 0.0;
    int    wcnt = 0;
#pragma unroll
    for (int r = 0; r < 4; r++) {
        int row = row0 + r;
        float dsq = 0.f, ssq = 0.f, sm = 0.f;
#pragma unroll
        for (int c = 0; c < 2; c++) {
            float4 v = x[r][c], cv = c ? cv1 : cv0;
            float dx = v.x - cv.x, dy = v.y - cv.y, dz = v.z - cv.z, dw = v.w - cv.w;
            dsq += dx*dx + dy*dy + dz*dz + dw*dw;
            ssq += v.x*v.x + v.y*v.y + v.z*v.z + v.w*v.w;
            sm  += v.x + v.y + v.z + v.w;
        }
#pragma unroll
        for (int o = 16; o > 0; o >>= 1) {
            dsq += __shfl_xor_sync(0xffffffffu, dsq, o);
            ssq += __shfl_xor_sync(0xffffffffu, ssq, o);
            sm  += __shfl_xor_sync(0xffffffffu, sm , o);
        }
        float inv_norm = 1.f / fmaxf(sqrtf(ssq), 1e-12f);
#pragma unroll
        for (int c = 0; c < 2; c++) {
            float4 v = x[r][c];
            int d0 = (c * 32 + lane) * 4;
            __nv_bfloat162 p0 = __floats2bfloat162_rn(v.x*inv_norm, v.y*inv_norm);
            __nv_bfloat162 p1 = __floats2bfloat162_rn(v.z*inv_norm, v.w*inv_norm);
            uint2 pk; pk.x = *(uint32_t*)&p0; pk.y = *(uint32_t*)&p1;
            *(uint2*)&g_fbf[(size_t)row * ND + d0] = pk;
        }
        if (lane == 0) {
            g_dsq[row] = dsq;
            g_accL0[row] = 0.f;
            g_accT[row]  = 0.f;
            if (lab[row] == 0) {
                wsum += (double)sm; wssq += (double)ssq;
                wctr += (double)dsq; wcnt++;
            }
        }
    }
    if (lane == 0) {
        sh_sm[wrp] = wsum; sh_ssq[wrp] = wssq; sh_ctr[wrp] = wctr; sh_cnt[wrp] = wcnt;
    }
    __syncthreads();
    if (threadIdx.x == 0) {
        double a = 0, b2 = 0, c2 = 0; int n = 0;
#pragma unroll
        for (int w = 0; w < 8; w++) { a += sh_sm[w]; b2 += sh_ssq[w]; c2 += sh_ctr[w]; n += sh_cnt[w]; }
        p_sum[blockIdx.x] = a; p_ssq[blockIdx.x] = b2;
        p_ctr[blockIdx.x] = c2; p_cnt[blockIdx.x] = n;
        __threadfence();
        unsigned t = atomicAdd(&g_tick_rs, 1u);
        s_last = (t == RSB - 1);
    }
    __syncthreads();

    if (s_last) {
        __shared__ double r0[256], r1[256], r2[256];
        __shared__ int    r3[256];
        int t = threadIdx.x;
        r0[t] = p_sum[t]; r1[t] = p_ssq[t]; r2[t] = p_ctr[t]; r3[t] = p_cnt[t];
        __syncthreads();
        for (int o = 128; o > 0; o >>= 1) {
            if (t < o) { r0[t] += r0[t+o]; r1[t] += r1[t+o]; r2[t] += r2[t+o]; r3[t] += r3[t+o]; }
            __syncthreads();
        }
        if (t == 0) {
            int cnt = r3[0];
            double n_el  = (double)cnt * (double)ND;
            double var   = (r1[0] - r0[0] * r0[0] / n_el) / (n_el - 1.0);
            double sigma = 0.9 * (double)rsig[0] + 0.1 * sqrt(var);
            g_m = (float)(0.5 + 0.3 * sigma + 0.3 * (1.0 - 224.0 / 900.0));
            g_center_d = r2[0];
            g_cnt = cnt;
            g_mc_d = 0.0;
            g_tick_rs = 0u;
        }
    }
}

// ---------------- pass 2: triangle-tiled bf16 mma contrastive ----------------
// 128x128 CTA tile, 8 warps (4x2), warp tile 32x64, BK=64, 3-stage cp.async.
// (no fused tail: keeps regs ~121, no spills)
__global__ void __launch_bounds__(256, 2) contrast_mma(const int* __restrict__ lab) {
    extern __shared__ __align__(16) char dsm[];
    __shared__ float s_w0c[BN];
    __shared__ float s_w0r[BM];

    int b = blockIdx.x;
    int ti = (int)((129.0 - sqrt(129.0 * 129.0 - 8.0 * (double)b)) * 0.5);
    int base = ti * NTILE - (ti * (ti - 1)) / 2;
    if (b < base) { ti--; base = ti * NTILE - (ti * (ti - 1)) / 2; }
    else if (b >= base + (NTILE - ti)) { ti++; base = ti * NTILE - (ti * (ti - 1)) / 2; }
    const int tj = ti + (b - base);

    const uint32_t sbase = smem_u32(dsm);
    const int tid = threadIdx.x, lane = tid & 31, wid = tid >> 5;
    const int wm = wid & 3, wn = wid >> 2;
    const int i0 = ti * BM, j0 = tj * BN;
    const bool diag = (ti == tj);

    for (int j = tid; j < BN; j += 256)
        s_w0c[j] = (lab[j0 + j] == 0) ? 1.f : 0.f;
    for (int i = tid; i < BM; i += 256)
        s_w0r[i] = (lab[i0 + i] == 0) ? 1.f : 0.f;

    float c[2][8][4];
#pragma unroll
    for (int fm = 0; fm < 2; fm++)
#pragma unroll
        for (int fn = 0; fn < 8; fn++)
#pragma unroll
            for (int e = 0; e < 4; e++) c[fm][fn][e] = 0.f;

    auto prefetch = [&](int kb) {
        uint32_t a_s = sbase + (uint32_t)(kb % 3) * 32768u;
        uint32_t b_s = a_s + 16384u;
        const __nv_bfloat16* gA = g_fbf + (size_t)i0 * ND + kb * BK;
        const __nv_bfloat16* gB = g_fbf + (size_t)j0 * ND + kb * BK;
#pragma unroll
        for (int it = 0; it < 4; it++) {
            int ch = tid + it * 256;
            int row = ch >> 3, c16 = ch & 7;
            uint32_t sw = (uint32_t)(row * 128 + ((c16 ^ (row & 7)) << 4));
            cp_async16(a_s + sw, gA + (size_t)row * ND + c16 * 8);
            cp_async16(b_s + sw, gB + (size_t)row * ND + c16 * 8);
        }
        asm volatile("cp.async.commit_group;" ::: "memory");
    };

    prefetch(0);
    prefetch(1);

#pragma unroll 1
    for (int kb = 0; kb < ND / BK; kb++) {
        if (kb < ND / BK - 1)
            asm volatile("cp.async.wait_group 1;" ::: "memory");
        else
            asm volatile("cp.async.wait_group 0;" ::: "memory");
        __syncthreads();
        if (kb + 2 < ND / BK) prefetch(kb + 2);

        uint32_t a_s = sbase + (uint32_t)(kb % 3) * 32768u;
        uint32_t b_s = a_s + 16384u;

#pragma unroll
        for (int ks = 0; ks < 4; ks++) {
            uint32_t a_frag[2][4], b_frag[4][4];
            int c16 = ks * 2 + (lane >> 4);
#pragma unroll
            for (int fm = 0; fm < 2; fm++) {
                int row = wm * 32 + fm * 16 + (lane & 15);
                ldsm_x4(a_frag[fm], a_s + row * 128 + ((c16 ^ (row & 7)) << 4));
            }
#pragma unroll
            for (int g = 0; g < 4; g++) {
                int row = wn * 64 + g * 16 + (lane & 15);
                ldsm_x4(b_frag[g], b_s + row * 128 + ((c16 ^ (row & 7)) << 4));
            }
#pragma unroll
            for (int fm = 0; fm < 2; fm++)
#pragma unroll
                for (int fn = 0; fn < 8; fn++) {
                    int g = fn >> 1;
                    uint32_t b0 = (fn & 1) ? b_frag[g][1] : b_frag[g][0];
                    uint32_t b1 = (fn & 1) ? b_frag[g][3] : b_frag[g][2];
                    mma16816(c[fm][fn], a_frag[fm], b0, b1);
                }
        }
    }

    // ---- epilogue (register-lean; fn outer, col partials short-lived) ----
    const int rl = wm * 32 + (lane >> 2);
    const int r_base = i0 + rl;
    float racc[8];
#pragma unroll
    for (int q = 0; q < 8; q++) racc[q] = 0.f;

    if (!diag) {
        float wr0 = s_w0r[rl], wr1 = s_w0r[rl + 8];
        float wr2 = s_w0r[rl + 16], wr3 = s_w0r[rl + 24];
#pragma unroll
        for (int fn = 0; fn < 8; fn++) {
            int jl = wn * 64 + fn * 8 + (lane & 3) * 2;
            float w0a = s_w0c[jl], w0b = s_w0c[jl + 1];
            float cTa = 0.f, cTb = 0.f, c0a = 0.f, c0b = 0.f;
#pragma unroll
            for (int fm = 0; fm < 2; fm++) {
                float e00 = ex2f(c[fm][fn][0] * CEXP);
                float e01 = ex2f(c[fm][fn][1] * CEXP);
                float e10 = ex2f(c[fm][fn][2] * CEXP);
                float e11 = ex2f(c[fm][fn][3] * CEXP);
                racc[fm*4+0] = fmaf(e00, w0a, fmaf(e01, w0b, racc[fm*4+0]));
                racc[fm*4+1] += e00 + e01;
                racc[fm*4+2] = fmaf(e10, w0a, fmaf(e11, w0b, racc[fm*4+2]));
                racc[fm*4+3] += e10 + e11;
                float wrA = fm ? wr2 : wr0, wrB = fm ? wr3 : wr1;
                cTa += e00 + e10; cTb += e01 + e11;
                c0a = fmaf(e00, wrA, fmaf(e10, wrB, c0a));
                c0b = fmaf(e01, wrA, fmaf(e11, wrB, c0b));
            }
#pragma unroll
            for (int o = 4; o <= 16; o <<= 1) {
                cTa += __shfl_xor_sync(0xffffffffu, cTa, o);
                cTb += __shfl_xor_sync(0xffffffffu, cTb, o);
                c0a += __shfl_xor_sync(0xffffffffu, c0a, o);
                c0b += __shfl_xor_sync(0xffffffffu, c0b, o);
            }
            if ((lane >> 2) == 0) {
                int jc = j0 + wn * 64 + fn * 8 + lane * 2;
                atomicAdd(&g_accT[jc],      cTa);
                atomicAdd(&g_accT[jc + 1],  cTb);
                atomicAdd(&g_accL0[jc],     c0a);
                atomicAdd(&g_accL0[jc + 1], c0b);
            }
        }
    } else {
#pragma unroll
        for (int fn = 0; fn < 8; fn++) {
            int jl = wn * 64 + fn * 8 + (lane & 3) * 2;
            int jg = j0 + jl;
            float w0a = s_w0c[jl], w0b = s_w0c[jl + 1];
#pragma unroll
            for (int fm = 0; fm < 2; fm++) {
                int r0 = r_base + fm * 16, r1 = r0 + 8;
                float e00 = ex2f(c[fm][fn][0] * CEXP);
                float e01 = ex2f(c[fm][fn][1] * CEXP);
                float e10 = ex2f(c[fm][fn][2] * CEXP);
                float e11 = ex2f(c[fm][fn][3] * CEXP);
                if (r0 == jg)     e00 = 0.f;
                if (r0 == jg + 1) e01 = 0.f;
                if (r1 == jg)     e10 = 0.f;
                if (r1 == jg + 1) e11 = 0.f;
                racc[fm*4+0] = fmaf(e00, w0a, fmaf(e01, w0b, racc[fm*4+0]));
                racc[fm*4+1] += e00 + e01;
                racc[fm*4+2] = fmaf(e10, w0a, fmaf(e11, w0b, racc[fm*4+2]));
                racc[fm*4+3] += e10 + e11;
            }
        }
    }

#pragma unroll
    for (int o = 1; o < 4; o <<= 1)
#pragma unroll
        for (int q = 0; q < 8; q++)
            racc[q] += __shfl_xor_sync(0xffffffffu, racc[q], o);

    if ((lane & 3) == 0) {
#pragma unroll
        for (int fm = 0; fm < 2; fm++) {
            int r0 = r_base + fm * 16, r1 = r0 + 8;
            atomicAdd(&g_accL0[r0], racc[fm*4+0]);
            atomicAdd(&g_accT[r0],  racc[fm*4+1]);
            atomicAdd(&g_accL0[r1], racc[fm*4+2]);
            atomicAdd(&g_accT[r1],  racc[fm*4+3]);
        }
    }
}

// ---------------- pass 3: per-row margin + contrastive + final write -------
// One double atomic per BLOCK (32 total), ticket-elected final write.
__global__ void con_final(const int* __restrict__ lab, float* __restrict__ out) {
    __shared__ double sh[8];
    __shared__ int s_last;
    int i = blockIdx.x * 256 + threadIdx.x;
    int lane = threadIdx.x & 31, wrp = threadIdx.x >> 5;
    int n0 = g_cnt, n1 = NB - n0;
    float m = g_m;

    int li = lab[i];
    float aT = g_accT[i], a0 = g_accL0[i];
    float pos = (li == 0) ? a0 : (aT - a0);
    int npos = ((li == 0) ? n0 : n1) - 1;
    int nneg = (li == 0) ? n1 : n0;
    float loc = 0.f;
    if (npos > 0 && nneg > 0)
        loc = 0.5f * (logf(aT + 1e-8f) - logf(pos));        // GAMMA*r_con
    if (li == 1)
        loc += fmaxf(m - sqrtf(g_dsq[i]), 0.f);             // BETA*r_margin
    double d = (double)loc;
#pragma unroll
    for (int o = 16; o > 0; o >>= 1)
        d += __shfl_xor_sync(0xffffffffu, d, o);
    if (lane == 0) sh[wrp] = d;
    __syncthreads();
    if (threadIdx.x == 0) {
        double s = 0.0;
#pragma unroll
        for (int w = 0; w < 8; w++) s += sh[w];
        atomicAdd(&g_mc_d, s);
        __threadfence();
        unsigned t = atomicAdd(&g_tick_cf, 1u);
        s_last = (t == (NB / 256) - 1);
        if (s_last) {
            g_tick_cf = 0u;
            out[0] = (float)((g_center_d + g_mc_d) / (double)NB);
        }
    }
}

// ---------------- launch ----------------
extern "C" void kernel_launch(void* const* d_in, const int* in_sizes, int n_in,
                              void* d_out, int out_size) {
    const float* feat = (const float*)d_in[0];
    const int*   lab  = (const int*)d_in[1];
    const float* cen  = (const float*)d_in[2];
    const float* rsig = (const float*)d_in[3];
    float* out = (float*)d_out;

    cudaFuncSetAttribute(contrast_mma,
                         cudaFuncAttributeMaxDynamicSharedMemorySize, 98304);

    row_stats<<<RSB, 256>>>(feat, lab, cen, rsig);
    contrast_mma<<<NBLK, 256, 98304>>>(lab);
    con_final<<<NB / 256, 256>>>(lab, out);
}

// round 14
// speedup vs baseline: 1.7749x; 1.0016x over previous
#include <cuda_runtime.h>
#include <cuda_bf16.h>
#include <math.h>
#include <stdint.h>

#define NB 8192
#define ND 256
#define BM 128
#define BN 128
#define BK 64
#define NTILE 64            // NB/BM
#define NBLK 2080           // NTILE*(NTILE+1)/2
#define RSB 512             // row_stats blocks (16 rows each)

// exp(sim/T) = exp2(sim * (log2e / T))
#define CEXP 20.6099291551f

// ---------------- scratch (no allocations allowed) ----------------
__device__ __nv_bfloat16 g_fbf[NB * ND];
__device__ float  g_dsq[NB];
__device__ float  g_accL0[NB];
__device__ float  g_accT[NB];
__device__ double p_sum[RSB], p_ssq[RSB], p_ctr[RSB];
__device__ int    p_cnt[RSB];
__device__ double g_center_d, g_mc_d;
__device__ float  g_m;
__device__ int    g_cnt;
__device__ unsigned g_tick_rs, g_tick_cf;

// ---------------- helpers ----------------
__device__ __forceinline__ uint32_t smem_u32(const void* p) {
    uint32_t a;
    asm("{ .reg .u64 t; cvta.to.shared.u64 t, %1; cvt.u32.u64 %0, t; }" : "=r"(a) : "l"(p));
    return a;
}
__device__ __forceinline__ float ex2f(float x) {
    float y; asm("ex2.approx.ftz.f32 %0, %1;" : "=f"(y) : "f"(x)); return y;
}
__device__ __forceinline__ void cp_async16(uint32_t s, const void* g) {
    asm volatile("cp.async.cg.shared.global [%0], [%1], 16;" :: "r"(s), "l"(g));
}
__device__ __forceinline__ void ldsm_x4(uint32_t* r, uint32_t addr) {
    asm volatile("ldmatrix.sync.aligned.m8n8.x4.shared.b16 {%0,%1,%2,%3}, [%4];"
                 : "=r"(r[0]), "=r"(r[1]), "=r"(r[2]), "=r"(r[3]) : "r"(addr));
}
__device__ __forceinline__ void mma16816(float* c, const uint32_t* a,
                                         uint32_t b0, uint32_t b1) {
    asm volatile("mma.sync.aligned.m16n8k16.row.col.f32.bf16.bf16.f32 "
                 "{%0,%1,%2,%3}, {%4,%5,%6,%7}, {%8,%9}, {%0,%1,%2,%3};"
                 : "+f"(c[0]), "+f"(c[1]), "+f"(c[2]), "+f"(c[3])
                 : "r"(a[0]), "r"(a[1]), "r"(a[2]), "r"(a[3]), "r"(b0), "r"(b1));
}

// ---------------- pass 1: stats + bf16 normalize (2 rows/warp, 512 blocks) --
__global__ void row_stats(const float* __restrict__ feat,
                          const int*   __restrict__ lab,
                          const float* __restrict__ cen,
                          const float* __restrict__ rsig) {
    __shared__ double sh_sm[8], sh_ssq[8], sh_ctr[8];
    __shared__ int    sh_cnt[8];
    __shared__ int    s_last;
    const int wrp  = threadIdx.x >> 5;
    const int lane = threadIdx.x & 31;
    const int row0 = blockIdx.x * 16 + wrp * 2;

    const float4* cr = (const float4*)cen;
    float4 cv0 = cr[lane], cv1 = cr[32 + lane];

    float4 x[2][2];
#pragma unroll
    for (int r = 0; r < 2; r++) {
        const float4* fr = (const float4*)(feat + (size_t)(row0 + r) * ND);
        x[r][0] = fr[lane];
        x[r][1] = fr[32 + lane];
    }

    double wsum = 0.0, wssq = 0.0, wctr = 0.0;
    int    wcnt = 0;
#pragma unroll
    for (int r = 0; r < 2; r++) {
        int row = row0 + r;
        float dsq = 0.f, ssq = 0.f, sm = 0.f;
#pragma unroll
        for (int c = 0; c < 2; c++) {
            float4 v = x[r][c], cv = c ? cv1 : cv0;
            float dx = v.x - cv.x, dy = v.y - cv.y, dz = v.z - cv.z, dw = v.w - cv.w;
            dsq += dx*dx + dy*dy + dz*dz + dw*dw;
            ssq += v.x*v.x + v.y*v.y + v.z*v.z + v.w*v.w;
            sm  += v.x + v.y + v.z + v.w;
        }
#pragma unroll
        for (int o = 16; o > 0; o >>= 1) {
            dsq += __shfl_xor_sync(0xffffffffu, dsq, o);
            ssq += __shfl_xor_sync(0xffffffffu, ssq, o);
            sm  += __shfl_xor_sync(0xffffffffu, sm , o);
        }
        float inv_norm = 1.f / fmaxf(sqrtf(ssq), 1e-12f);
#pragma unroll
        for (int c = 0; c < 2; c++) {
            float4 v = x[r][c];
            int d0 = (c * 32 + lane) * 4;
            __nv_bfloat162 p0 = __floats2bfloat162_rn(v.x*inv_norm, v.y*inv_norm);
            __nv_bfloat162 p1 = __floats2bfloat162_rn(v.z*inv_norm, v.w*inv_norm);
            uint2 pk; pk.x = *(uint32_t*)&p0; pk.y = *(uint32_t*)&p1;
            *(uint2*)&g_fbf[(size_t)row * ND + d0] = pk;
        }
        if (lane == 0) {
            g_dsq[row] = dsq;
            g_accL0[row] = 0.f;
            g_accT[row]  = 0.f;
            if (lab[row] == 0) {
                wsum += (double)sm; wssq += (double)ssq;
                wctr += (double)dsq; wcnt++;
            }
        }
    }
    if (lane == 0) {
        sh_sm[wrp] = wsum; sh_ssq[wrp] = wssq; sh_ctr[wrp] = wctr; sh_cnt[wrp] = wcnt;
    }
    __syncthreads();
    if (threadIdx.x == 0) {
        double a = 0, b2 = 0, c2 = 0; int n = 0;
#pragma unroll
        for (int w = 0; w < 8; w++) { a += sh_sm[w]; b2 += sh_ssq[w]; c2 += sh_ctr[w]; n += sh_cnt[w]; }
        p_sum[blockIdx.x] = a; p_ssq[blockIdx.x] = b2;
        p_ctr[blockIdx.x] = c2; p_cnt[blockIdx.x] = n;
        __threadfence();
        unsigned t = atomicAdd(&g_tick_rs, 1u);
        s_last = (t == RSB - 1);
    }
    __syncthreads();

    if (s_last) {
        __shared__ double r0[256], r1[256], r2[256];
        __shared__ int    r3[256];
        int t = threadIdx.x;
        double a = 0, b = 0, c = 0; int n = 0;
#pragma unroll
        for (int q = 0; q < RSB / 256; q++) {
            int idx = t + q * 256;
            a += p_sum[idx]; b += p_ssq[idx]; c += p_ctr[idx]; n += p_cnt[idx];
        }
        r0[t] = a; r1[t] = b; r2[t] = c; r3[t] = n;
        __syncthreads();
        for (int o = 128; o > 0; o >>= 1) {
            if (t < o) { r0[t] += r0[t+o]; r1[t] += r1[t+o]; r2[t] += r2[t+o]; r3[t] += r3[t+o]; }
            __syncthreads();
        }
        if (t == 0) {
            int cnt = r3[0];
            double n_el  = (double)cnt * (double)ND;
            double var   = (r1[0] - r0[0] * r0[0] / n_el) / (n_el - 1.0);
            double sigma = 0.9 * (double)rsig[0] + 0.1 * sqrt(var);
            g_m = (float)(0.5 + 0.3 * sigma + 0.3 * (1.0 - 224.0 / 900.0));
            g_center_d = r2[0];
            g_cnt = cnt;
            g_mc_d = 0.0;
            g_tick_rs = 0u;
        }
    }
}

// ---------------- pass 2: triangle-tiled bf16 mma contrastive ----------------
// 128x128 CTA tile, 8 warps (4x2), warp tile 32x64, BK=64, 3-stage cp.async.
__global__ void __launch_bounds__(256, 2) contrast_mma(const int* __restrict__ lab) {
    extern __shared__ __align__(16) char dsm[];
    __shared__ float s_w0c[BN];
    __shared__ float s_w0r[BM];

    int b = blockIdx.x;
    int ti = (int)((129.0 - sqrt(129.0 * 129.0 - 8.0 * (double)b)) * 0.5);
    int base = ti * NTILE - (ti * (ti - 1)) / 2;
    if (b < base) { ti--; base = ti * NTILE - (ti * (ti - 1)) / 2; }
    else if (b >= base + (NTILE - ti)) { ti++; base = ti * NTILE - (ti * (ti - 1)) / 2; }
    const int tj = ti + (b - base);

    const uint32_t sbase = smem_u32(dsm);
    const int tid = threadIdx.x, lane = tid & 31, wid = tid >> 5;
    const int wm = wid & 3, wn = wid >> 2;
    const int i0 = ti * BM, j0 = tj * BN;
    const bool diag = (ti == tj);

    for (int j = tid; j < BN; j += 256)
        s_w0c[j] = (lab[j0 + j] == 0) ? 1.f : 0.f;
    for (int i = tid; i < BM; i += 256)
        s_w0r[i] = (lab[i0 + i] == 0) ? 1.f : 0.f;

    float c[2][8][4];
#pragma unroll
    for (int fm = 0; fm < 2; fm++)
#pragma unroll
        for (int fn = 0; fn < 8; fn++)
#pragma unroll
            for (int e = 0; e < 4; e++) c[fm][fn][e] = 0.f;

    auto prefetch = [&](int kb) {
        uint32_t a_s = sbase + (uint32_t)(kb % 3) * 32768u;
        uint32_t b_s = a_s + 16384u;
        const __nv_bfloat16* gA = g_fbf + (size_t)i0 * ND + kb * BK;
        const __nv_bfloat16* gB = g_fbf + (size_t)j0 * ND + kb * BK;
#pragma unroll
        for (int it = 0; it < 4; it++) {
            int ch = tid + it * 256;
            int row = ch >> 3, c16 = ch & 7;
            uint32_t sw = (uint32_t)(row * 128 + ((c16 ^ (row & 7)) << 4));
            cp_async16(a_s + sw, gA + (size_t)row * ND + c16 * 8);
            cp_async16(b_s + sw, gB + (size_t)row * ND + c16 * 8);
        }
        asm volatile("cp.async.commit_group;" ::: "memory");
    };

    prefetch(0);
    prefetch(1);

#pragma unroll 1
    for (int kb = 0; kb < ND / BK; kb++) {
        if (kb < ND / BK - 1)
            asm volatile("cp.async.wait_group 1;" ::: "memory");
        else
            asm volatile("cp.async.wait_group 0;" ::: "memory");
        __syncthreads();
        if (kb + 2 < ND / BK) prefetch(kb + 2);

        uint32_t a_s = sbase + (uint32_t)(kb % 3) * 32768u;
        uint32_t b_s = a_s + 16384u;

#pragma unroll
        for (int ks = 0; ks < 4; ks++) {
            uint32_t a_frag[2][4], b_frag[4][4];
            int c16 = ks * 2 + (lane >> 4);
#pragma unroll
            for (int fm = 0; fm < 2; fm++) {
                int row = wm * 32 + fm * 16 + (lane & 15);
                ldsm_x4(a_frag[fm], a_s + row * 128 + ((c16 ^ (row & 7)) << 4));
            }
#pragma unroll
            for (int g = 0; g < 4; g++) {
                int row = wn * 64 + g * 16 + (lane & 15);
                ldsm_x4(b_frag[g], b_s + row * 128 + ((c16 ^ (row & 7)) << 4));
            }
#pragma unroll
            for (int fm = 0; fm < 2; fm++)
#pragma unroll
                for (int fn = 0; fn < 8; fn++) {
                    int g = fn >> 1;
                    uint32_t b0 = (fn & 1) ? b_frag[g][1] : b_frag[g][0];
                    uint32_t b1 = (fn & 1) ? b_frag[g][3] : b_frag[g][2];
                    mma16816(c[fm][fn], a_frag[fm], b0, b1);
                }
        }
    }

    // ---- epilogue (register-lean; fn outer, col partials short-lived) ----
    const int rl = wm * 32 + (lane >> 2);
    const int r_base = i0 + rl;
    float racc[8];
#pragma unroll
    for (int q = 0; q < 8; q++) racc[q] = 0.f;

    if (!diag) {
        float wr0 = s_w0r[rl], wr1 = s_w0r[rl + 8];
        float wr2 = s_w0r[rl + 16], wr3 = s_w0r[rl + 24];
#pragma unroll
        for (int fn = 0; fn < 8; fn++) {
            int jl = wn * 64 + fn * 8 + (lane & 3) * 2;
            float w0a = s_w0c[jl], w0b = s_w0c[jl + 1];
            float cTa = 0.f, cTb = 0.f, c0a = 0.f, c0b = 0.f;
#pragma unroll
            for (int fm = 0; fm < 2; fm++) {
                float e00 = ex2f(c[fm][fn][0] * CEXP);
                float e01 = ex2f(c[fm][fn][1] * CEXP);
                float e10 = ex2f(c[fm][fn][2] * CEXP);
                float e11 = ex2f(c[fm][fn][3] * CEXP);
                racc[fm*4+0] = fmaf(e00, w0a, fmaf(e01, w0b, racc[fm*4+0]));
                racc[fm*4+1] += e00 + e01;
                racc[fm*4+2] = fmaf(e10, w0a, fmaf(e11, w0b, racc[fm*4+2]));
                racc[fm*4+3] += e10 + e11;
                float wrA = fm ? wr2 : wr0, wrB = fm ? wr3 : wr1;
                cTa += e00 + e10; cTb += e01 + e11;
                c0a = fmaf(e00, wrA, fmaf(e10, wrB, c0a));
                c0b = fmaf(e01, wrA, fmaf(e11, wrB, c0b));
            }
#pragma unroll
            for (int o = 4; o <= 16; o <<= 1) {
                cTa += __shfl_xor_sync(0xffffffffu, cTa, o);
                cTb += __shfl_xor_sync(0xffffffffu, cTb, o);
                c0a += __shfl_xor_sync(0xffffffffu, c0a, o);
                c0b += __shfl_xor_sync(0xffffffffu, c0b, o);
            }
            if ((lane >> 2) == 0) {
                int jc = j0 + wn * 64 + fn * 8 + lane * 2;
                atomicAdd(&g_accT[jc],      cTa);
                atomicAdd(&g_accT[jc + 1],  cTb);
                atomicAdd(&g_accL0[jc],     c0a);
                atomicAdd(&g_accL0[jc + 1], c0b);
            }
        }
    } else {
#pragma unroll
        for (int fn = 0; fn < 8; fn++) {
            int jl = wn * 64 + fn * 8 + (lane & 3) * 2;
            int jg = j0 + jl;
            float w0a = s_w0c[jl], w0b = s_w0c[jl + 1];
#pragma unroll
            for (int fm = 0; fm < 2; fm++) {
                int r0 = r_base + fm * 16, r1 = r0 + 8;
                float e00 = ex2f(c[fm][fn][0] * CEXP);
                float e01 = ex2f(c[fm][fn][1] * CEXP);
                float e10 = ex2f(c[fm][fn][2] * CEXP);
                float e11 = ex2f(c[fm][fn][3] * CEXP);
                if (r0 == jg)     e00 = 0.f;
                if (r0 == jg + 1) e01 = 0.f;
                if (r1 == jg)     e10 = 0.f;
                if (r1 == jg + 1) e11 = 0.f;
                racc[fm*4+0] = fmaf(e00, w0a, fmaf(e01, w0b, racc[fm*4+0]));
                racc[fm*4+1] += e00 + e01;
                racc[fm*4+2] = fmaf(e10, w0a, fmaf(e11, w0b, racc[fm*4+2]));
                racc[fm*4+3] += e10 + e11;
            }
        }
    }

#pragma unroll
    for (int o = 1; o < 4; o <<= 1)
#pragma unroll
        for (int q = 0; q < 8; q++)
            racc[q] += __shfl_xor_sync(0xffffffffu, racc[q], o);

    if ((lane & 3) == 0) {
#pragma unroll
        for (int fm = 0; fm < 2; fm++) {
            int r0 = r_base + fm * 16, r1 = r0 + 8;
            atomicAdd(&g_accL0[r0], racc[fm*4+0]);
            atomicAdd(&g_accT[r0],  racc[fm*4+1]);
            atomicAdd(&g_accL0[r1], racc[fm*4+2]);
            atomicAdd(&g_accT[r1],  racc[fm*4+3]);
        }
    }
}

// ---------------- pass 3: per-row margin + contrastive + final write -------
__global__ void con_final(const int* __restrict__ lab, float* __restrict__ out) {
    __shared__ double sh[8];
    __shared__ int s_last;
    int i = blockIdx.x * 256 + threadIdx.x;
    int lane = threadIdx.x & 31, wrp = threadIdx.x >> 5;
    int n0 = g_cnt, n1 = NB - n0;
    float m = g_m;

    int li = lab[i];
    float aT = g_accT[i], a0 = g_accL0[i];
    float pos = (li == 0) ? a0 : (aT - a0);
    int npos = ((li == 0) ? n0 : n1) - 1;
    int nneg = (li == 0) ? n1 : n0;
    float loc = 0.f;
    if (npos > 0 && nneg > 0)
        loc = 0.5f * (logf(aT + 1e-8f) - logf(pos));        // GAMMA*r_con
    if (li == 1)
        loc += fmaxf(m - sqrtf(g_dsq[i]), 0.f);             // BETA*r_margin
    double d = (double)loc;
#pragma unroll
    for (int o = 16; o > 0; o >>= 1)
        d += __shfl_xor_sync(0xffffffffu, d, o);
    if (lane == 0) sh[wrp] = d;
    __syncthreads();
    if (threadIdx.x == 0) {
        double s = 0.0;
#pragma unroll
        for (int w = 0; w < 8; w++) s += sh[w];
        atomicAdd(&g_mc_d, s);
        __threadfence();
        unsigned t = atomicAdd(&g_tick_cf, 1u);
        s_last = (t == (NB / 256) - 1);
        if (s_last) {
            g_tick_cf = 0u;
            out[0] = (float)((g_center_d + g_mc_d) / (double)NB);
        }
    }
}

// ---------------- launch ----------------
extern "C" void kernel_launch(void* const* d_in, const int* in_sizes, int n_in,
                              void* d_out, int out_size) {
    const float* feat = (const float*)d_in[0];
    const int*   lab  = (const int*)d_in[1];
    const float* cen  = (const float*)d_in[2];
    const float* rsig = (const float*)d_in[3];
    float* out = (float*)d_out;

    cudaFuncSetAttribute(contrast_mma,
                         cudaFuncAttributeMaxDynamicSharedMemorySize, 98304);

    row_stats<<<RSB, 256>>>(feat, lab, cen, rsig);
    contrast_mma<<<NBLK, 256, 98304>>>(lab);
    con_final<<<NB / 256, 256>>>(lab, out);
}

// round 16
// speedup vs baseline: 1.7843x; 1.0053x over previous
#include <cuda_runtime.h>
#include <cuda_bf16.h>
#include <math.h>
#include <stdint.h>

#define NB 8192
#define ND 256
#define BM 128
#define BN 128
#define NKB 2               // k-blocks of 128 fp8
#define NTILE 64            // NB/BM
#define NBLK 2080           // NTILE*(NTILE+1)/2
#define RSB 512             // row_stats blocks (16 rows each)

// exp(sim/T) = exp2(sim * (log2e / T))
#define CEXP 20.6099291551f

// ---------------- scratch (no allocations allowed) ----------------
__device__ uint8_t g_f8[NB * ND];          // normalized features, e4m3 (2 MB)
__device__ float  g_dsq[NB];
__device__ float  g_accL0[NB];
__device__ float  g_accT[NB];
__device__ double p_sum[RSB], p_ssq[RSB], p_ctr[RSB];
__device__ int    p_cnt[RSB];
__device__ double g_center_d, g_mc_d;
__device__ float  g_m;
__device__ int    g_cnt;
__device__ unsigned g_tick_rs, g_tick_cf;

// ---------------- helpers ----------------
__device__ __forceinline__ uint32_t smem_u32(const void* p) {
    uint32_t a;
    asm("{ .reg .u64 t; cvta.to.shared.u64 t, %1; cvt.u32.u64 %0, t; }" : "=r"(a) : "l"(p));
    return a;
}
__device__ __forceinline__ float ex2f(float x) {
    float y; asm("ex2.approx.ftz.f32 %0, %1;" : "=f"(y) : "f"(x)); return y;
}
__device__ __forceinline__ void cp_async16(uint32_t s, const void* g) {
    asm volatile("cp.async.cg.shared.global [%0], [%1], 16;" :: "r"(s), "l"(g));
}
__device__ __forceinline__ void ldsm_x4(uint32_t* r, uint32_t addr) {
    asm volatile("ldmatrix.sync.aligned.m8n8.x4.shared.b16 {%0,%1,%2,%3}, [%4];"
                 : "=r"(r[0]), "=r"(r[1]), "=r"(r[2]), "=r"(r[3]) : "r"(addr));
}
// fp8 e4m3 mma: D[16x8] += A[16x32] * B[32x8]
__device__ __forceinline__ void mma16832(float* c, const uint32_t* a,
                                         uint32_t b0, uint32_t b1) {
    asm volatile("mma.sync.aligned.m16n8k32.row.col.f32.e4m3.e4m3.f32 "
                 "{%0,%1,%2,%3}, {%4,%5,%6,%7}, {%8,%9}, {%0,%1,%2,%3};"
                 : "+f"(c[0]), "+f"(c[1]), "+f"(c[2]), "+f"(c[3])
                 : "r"(a[0]), "r"(a[1]), "r"(a[2]), "r"(a[3]), "r"(b0), "r"(b1));
}
// pack 4 floats -> 4 e4m3 bytes (k-ascending, little-endian)
__device__ __forceinline__ uint32_t pack_e4m3_4(float v0, float v1, float v2, float v3) {
    uint16_t lo, hi;
    asm("cvt.rn.satfinite.e4m3x2.f32 %0, %1, %2;" : "=h"(lo) : "f"(v1), "f"(v0));
    asm("cvt.rn.satfinite.e4m3x2.f32 %0, %1, %2;" : "=h"(hi) : "f"(v3), "f"(v2));
    return (uint32_t)lo | ((uint32_t)hi << 16);
}

// ---------------- pass 1: stats + e4m3 normalize (2 rows/warp) ----------------
__global__ void row_stats(const float* __restrict__ feat,
                          const int*   __restrict__ lab,
                          const float* __restrict__ cen,
                          const float* __restrict__ rsig) {
    __shared__ double sh_sm[8], sh_ssq[8], sh_ctr[8];
    __shared__ int    sh_cnt[8];
    __shared__ int    s_last;
    const int wrp  = threadIdx.x >> 5;
    const int lane = threadIdx.x & 31;
    const int row0 = blockIdx.x * 16 + wrp * 2;

    const float4* cr = (const float4*)cen;
    float4 cv0 = cr[lane], cv1 = cr[32 + lane];

    float4 x[2][2];
#pragma unroll
    for (int r = 0; r < 2; r++) {
        const float4* fr = (const float4*)(feat + (size_t)(row0 + r) * ND);
        x[r][0] = fr[lane];
        x[r][1] = fr[32 + lane];
    }

    double wsum = 0.0, wssq = 0.0, wctr = 0.0;
    int    wcnt = 0;
#pragma unroll
    for (int r = 0; r < 2; r++) {
        int row = row0 + r;
        float dsq = 0.f, ssq = 0.f, sm = 0.f;
#pragma unroll
        for (int c = 0; c < 2; c++) {
            float4 v = x[r][c], cv = c ? cv1 : cv0;
            float dx = v.x - cv.x, dy = v.y - cv.y, dz = v.z - cv.z, dw = v.w - cv.w;
            dsq += dx*dx + dy*dy + dz*dz + dw*dw;
            ssq += v.x*v.x + v.y*v.y + v.z*v.z + v.w*v.w;
            sm  += v.x + v.y + v.z + v.w;
        }
#pragma unroll
        for (int o = 16; o > 0; o >>= 1) {
            dsq += __shfl_xor_sync(0xffffffffu, dsq, o);
            ssq += __shfl_xor_sync(0xffffffffu, ssq, o);
            sm  += __shfl_xor_sync(0xffffffffu, sm , o);
        }
        float inv_norm = 1.f / fmaxf(sqrtf(ssq), 1e-12f);
#pragma unroll
        for (int c = 0; c < 2; c++) {
            float4 v = x[r][c];
            int d0 = (c * 32 + lane) * 4;
            uint32_t w = pack_e4m3_4(v.x*inv_norm, v.y*inv_norm,
                                     v.z*inv_norm, v.w*inv_norm);
            *(uint32_t*)&g_f8[(size_t)row * ND + d0] = w;
        }
        if (lane == 0) {
            g_dsq[row] = dsq;
            g_accL0[row] = 0.f;
            g_accT[row]  = 0.f;
            if (lab[row] == 0) {
                wsum += (double)sm; wssq += (double)ssq;
                wctr += (double)dsq; wcnt++;
            }
        }
    }
    if (lane == 0) {
        sh_sm[wrp] = wsum; sh_ssq[wrp] = wssq; sh_ctr[wrp] = wctr; sh_cnt[wrp] = wcnt;
    }
    __syncthreads();
    if (threadIdx.x == 0) {
        double a = 0, b2 = 0, c2 = 0; int n = 0;
#pragma unroll
        for (int w = 0; w < 8; w++) { a += sh_sm[w]; b2 += sh_ssq[w]; c2 += sh_ctr[w]; n += sh_cnt[w]; }
        p_sum[blockIdx.x] = a; p_ssq[blockIdx.x] = b2;
        p_ctr[blockIdx.x] = c2; p_cnt[blockIdx.x] = n;
        __threadfence();
        unsigned t = atomicAdd(&g_tick_rs, 1u);
        s_last = (t == RSB - 1);
    }
    __syncthreads();

    if (s_last) {
        __shared__ double r0[256], r1[256], r2[256];
        __shared__ int    r3[256];
        int t = threadIdx.x;
        double a = 0, b = 0, c = 0; int n = 0;
#pragma unroll
        for (int q = 0; q < RSB / 256; q++) {
            int idx = t + q * 256;
            a += p_sum[idx]; b += p_ssq[idx]; c += p_ctr[idx]; n += p_cnt[idx];
        }
        r0[t] = a; r1[t] = b; r2[t] = c; r3[t] = n;
        __syncthreads();
        for (int o = 128; o > 0; o >>= 1) {
            if (t < o) { r0[t] += r0[t+o]; r1[t] += r1[t+o]; r2[t] += r2[t+o]; r3[t] += r3[t+o]; }
            __syncthreads();
        }
        if (t == 0) {
            int cnt = r3[0];
            double n_el  = (double)cnt * (double)ND;
            double var   = (r1[0] - r0[0] * r0[0] / n_el) / (n_el - 1.0);
            double sigma = 0.9 * (double)rsig[0] + 0.1 * sqrt(var);
            g_m = (float)(0.5 + 0.3 * sigma + 0.3 * (1.0 - 224.0 / 900.0));
            g_center_d = r2[0];
            g_cnt = cnt;
            g_mc_d = 0.0;
            g_tick_rs = 0u;
        }
    }
}

// ---------------- pass 2: triangle-tiled FP8 mma contrastive ----------------
// 128x128 CTA tile, 8 warps (4x2), warp tile 32x64, BK=128 fp8, 2 k-blocks.
__global__ void __launch_bounds__(256, 2) contrast_mma(const int* __restrict__ lab) {
    extern __shared__ __align__(16) char dsm[];
    __shared__ float s_w0c[BN];
    __shared__ float s_w0r[BM];

    int b = blockIdx.x;
    int ti = (int)((129.0 - sqrt(129.0 * 129.0 - 8.0 * (double)b)) * 0.5);
    int base = ti * NTILE - (ti * (ti - 1)) / 2;
    if (b < base) { ti--; base = ti * NTILE - (ti * (ti - 1)) / 2; }
    else if (b >= base + (NTILE - ti)) { ti++; base = ti * NTILE - (ti * (ti - 1)) / 2; }
    const int tj = ti + (b - base);

    const uint32_t sbase = smem_u32(dsm);
    const int tid = threadIdx.x, lane = tid & 31, wid = tid >> 5;
    const int wm = wid & 3, wn = wid >> 2;
    const int i0 = ti * BM, j0 = tj * BN;
    const bool diag = (ti == tj);

    for (int j = tid; j < BN; j += 256)
        s_w0c[j] = (lab[j0 + j] == 0) ? 1.f : 0.f;
    for (int i = tid; i < BM; i += 256)
        s_w0r[i] = (lab[i0 + i] == 0) ? 1.f : 0.f;

    float c[2][8][4];
#pragma unroll
    for (int fm = 0; fm < 2; fm++)
#pragma unroll
        for (int fn = 0; fn < 8; fn++)
#pragma unroll
            for (int e = 0; e < 4; e++) c[fm][fn][e] = 0.f;

    // prefetch k-block kb (A 16KB + B 16KB, 128B rows of fp8)
    auto prefetch = [&](int kb) {
        uint32_t a_s = sbase + (uint32_t)kb * 32768u;
        uint32_t b_s = a_s + 16384u;
        const uint8_t* gA = g_f8 + (size_t)i0 * ND + kb * 128;
        const uint8_t* gB = g_f8 + (size_t)j0 * ND + kb * 128;
#pragma unroll
        for (int it = 0; it < 4; it++) {
            int ch = tid + it * 256;             // 1024 chunks of 16B per tile
            int row = ch >> 3, c16 = ch & 7;
            uint32_t sw = (uint32_t)(row * 128 + ((c16 ^ (row & 7)) << 4));
            cp_async16(a_s + sw, gA + (size_t)row * ND + c16 * 16);
            cp_async16(b_s + sw, gB + (size_t)row * ND + c16 * 16);
        }
        asm volatile("cp.async.commit_group;" ::: "memory");
    };

    prefetch(0);
    prefetch(1);

#pragma unroll 1
    for (int kb = 0; kb < NKB; kb++) {
        if (kb == 0)
            asm volatile("cp.async.wait_group 1;" ::: "memory");
        else
            asm volatile("cp.async.wait_group 0;" ::: "memory");
        __syncthreads();

        uint32_t a_s = sbase + (uint32_t)kb * 32768u;
        uint32_t b_s = a_s + 16384u;

#pragma unroll
        for (int ks = 0; ks < 4; ks++) {         // each ks = k32 fp8
            uint32_t a_frag[2][4], b_frag[4][4];
            int c16 = ks * 2 + (lane >> 4);
#pragma unroll
            for (int fm = 0; fm < 2; fm++) {
                int row = wm * 32 + fm * 16 + (lane & 15);
                ldsm_x4(a_frag[fm], a_s + row * 128 + ((c16 ^ (row & 7)) << 4));
            }
#pragma unroll
            for (int g = 0; g < 4; g++) {
                int row = wn * 64 + g * 16 + (lane & 15);
                ldsm_x4(b_frag[g], b_s + row * 128 + ((c16 ^ (row & 7)) << 4));
            }
#pragma unroll
            for (int fm = 0; fm < 2; fm++)
#pragma unroll
                for (int fn = 0; fn < 8; fn++) {
                    int g = fn >> 1;
                    uint32_t b0 = (fn & 1) ? b_frag[g][1] : b_frag[g][0];
                    uint32_t b1 = (fn & 1) ? b_frag[g][3] : b_frag[g][2];
                    mma16832(c[fm][fn], a_frag[fm], b0, b1);
                }
        }
    }

    // ---- epilogue (register-lean; fn outer, col partials short-lived) ----
    const int rl = wm * 32 + (lane >> 2);
    const int r_base = i0 + rl;
    float racc[8];
#pragma unroll
    for (int q = 0; q < 8; q++) racc[q] = 0.f;

    if (!diag) {
        float wr0 = s_w0r[rl], wr1 = s_w0r[rl + 8];
        float wr2 = s_w0r[rl + 16], wr3 = s_w0r[rl + 24];
#pragma unroll
        for (int fn = 0; fn < 8; fn++) {
            int jl = wn * 64 + fn * 8 + (lane & 3) * 2;
            float w0a = s_w0c[jl], w0b = s_w0c[jl + 1];
            float cTa = 0.f, cTb = 0.f, c0a = 0.f, c0b = 0.f;
#pragma unroll
            for (int fm = 0; fm < 2; fm++) {
                float e00 = ex2f(c[fm][fn][0] * CEXP);
                float e01 = ex2f(c[fm][fn][1] * CEXP);
                float e10 = ex2f(c[fm][fn][2] * CEXP);
                float e11 = ex2f(c[fm][fn][3] * CEXP);
                racc[fm*4+0] = fmaf(e00, w0a, fmaf(e01, w0b, racc[fm*4+0]));
                racc[fm*4+1] += e00 + e01;
                racc[fm*4+2] = fmaf(e10, w0a, fmaf(e11, w0b, racc[fm*4+2]));
                racc[fm*4+3] += e10 + e11;
                float wrA = fm ? wr2 : wr0, wrB = fm ? wr3 : wr1;
                cTa += e00 + e10; cTb += e01 + e11;
                c0a = fmaf(e00, wrA, fmaf(e10, wrB, c0a));
                c0b = fmaf(e01, wrA, fmaf(e11, wrB, c0b));
            }
#pragma unroll
            for (int o = 4; o <= 16; o <<= 1) {
                cTa += __shfl_xor_sync(0xffffffffu, cTa, o);
                cTb += __shfl_xor_sync(0xffffffffu, cTb, o);
                c0a += __shfl_xor_sync(0xffffffffu, c0a, o);
                c0b += __shfl_xor_sync(0xffffffffu, c0b, o);
            }
            if ((lane >> 2) == 0) {
                int jc = j0 + wn * 64 + fn * 8 + lane * 2;
                atomicAdd(&g_accT[jc],      cTa);
                atomicAdd(&g_accT[jc + 1],  cTb);
                atomicAdd(&g_accL0[jc],     c0a);
                atomicAdd(&g_accL0[jc + 1], c0b);
            }
        }
    } else {
#pragma unroll
        for (int fn = 0; fn < 8; fn++) {
            int jl = wn * 64 + fn * 8 + (lane & 3) * 2;
            int jg = j0 + jl;
            float w0a = s_w0c[jl], w0b = s_w0c[jl + 1];
#pragma unroll
            for (int fm = 0; fm < 2; fm++) {
                int r0 = r_base + fm * 16, r1 = r0 + 8;
                float e00 = ex2f(c[fm][fn][0] * CEXP);
                float e01 = ex2f(c[fm][fn][1] * CEXP);
                float e10 = ex2f(c[fm][fn][2] * CEXP);
                float e11 = ex2f(c[fm][fn][3] * CEXP);
                if (r0 == jg)     e00 = 0.f;
                if (r0 == jg + 1) e01 = 0.f;
                if (r1 == jg)     e10 = 0.f;
                if (r1 == jg + 1) e11 = 0.f;
                racc[fm*4+0] = fmaf(e00, w0a, fmaf(e01, w0b, racc[fm*4+0]));
                racc[fm*4+1] += e00 + e01;
                racc[fm*4+2] = fmaf(e10, w0a, fmaf(e11, w0b, racc[fm*4+2]));
                racc[fm*4+3] += e10 + e11;
            }
        }
    }

#pragma unroll
    for (int o = 1; o < 4; o <<= 1)
#pragma unroll
        for (int q = 0; q < 8; q++)
            racc[q] += __shfl_xor_sync(0xffffffffu, racc[q], o);

    if ((lane & 3) == 0) {
#pragma unroll
        for (int fm = 0; fm < 2; fm++) {
            int r0 = r_base + fm * 16, r1 = r0 + 8;
            atomicAdd(&g_accL0[r0], racc[fm*4+0]);
            atomicAdd(&g_accT[r0],  racc[fm*4+1]);
            atomicAdd(&g_accL0[r1], racc[fm*4+2]);
            atomicAdd(&g_accT[r1],  racc[fm*4+3]);
        }
    }
}

// ---------------- pass 3: per-row margin + contrastive + final write -------
__global__ void con_final(const int* __restrict__ lab, float* __restrict__ out) {
    __shared__ double sh[8];
    __shared__ int s_last;
    int i = blockIdx.x * 256 + threadIdx.x;
    int lane = threadIdx.x & 31, wrp = threadIdx.x >> 5;
    int n0 = g_cnt, n1 = NB - n0;
    float m = g_m;

    int li = lab[i];
    float aT = g_accT[i], a0 = g_accL0[i];
    float pos = (li == 0) ? a0 : (aT - a0);
    int npos = ((li == 0) ? n0 : n1) - 1;
    int nneg = (li == 0) ? n1 : n0;
    float loc = 0.f;
    if (npos > 0 && nneg > 0)
        loc = 0.5f * (logf(aT + 1e-8f) - logf(pos));        // GAMMA*r_con
    if (li == 1)
        loc += fmaxf(m - sqrtf(g_dsq[i]), 0.f);             // BETA*r_margin
    double d = (double)loc;
#pragma unroll
    for (int o = 16; o > 0; o >>= 1)
        d += __shfl_xor_sync(0xffffffffu, d, o);
    if (lane == 0) sh[wrp] = d;
    __syncthreads();
    if (threadIdx.x == 0) {
        double s = 0.0;
#pragma unroll
        for (int w = 0; w < 8; w++) s += sh[w];
        atomicAdd(&g_mc_d, s);
        __threadfence();
        unsigned t = atomicAdd(&g_tick_cf, 1u);
        s_last = (t == (NB / 256) - 1);
        if (s_last) {
            g_tick_cf = 0u;
            out[0] = (float)((g_center_d + g_mc_d) / (double)NB);
        }
    }
}

// ---------------- launch ----------------
extern "C" void kernel_launch(void* const* d_in, const int* in_sizes, int n_in,
                              void* d_out, int out_size) {
    const float* feat = (const float*)d_in[0];
    const int*   lab  = (const int*)d_in[1];
    const float* cen  = (const float*)d_in[2];
    const float* rsig = (const float*)d_in[3];
    float* out = (float*)d_out;

    cudaFuncSetAttribute(contrast_mma,
                         cudaFuncAttributeMaxDynamicSharedMemorySize, 65536);

    row_stats<<<RSB, 256>>>(feat, lab, cen, rsig);
    contrast_mma<<<NBLK, 256, 65536>>>(lab);
    con_final<<<NB / 256, 256>>>(lab, out);
}